// round 3
// baseline (speedup 1.0000x reference)
#include <cuda_runtime.h>
#include <cstdint>

#define NN   25000
#define NE   100000
#define HD   32
#define NCL  8000
#define NA   50000
#define NEC  24000
#define EDIM 8

#define TILE 128                 // nodes per fused block
#define NBK_N 196                // cdiv(NN,128)
#define NBK_C 63                 // cdiv(NCL,128)

typedef unsigned long long u64;

// ---------------- scratch -------------------------------------------------------
__device__ float g_x[NN * HD];
__device__ float g_c[NCL * HD];
__device__ float g_h[NE * HD];
__device__ float g_aggn[NN * HD];
__device__ float g_aggc[NCL * HD];
__device__ float g_m[NN * HD];
__device__ int   g_ints[2 * NN + 2 * NCL + 2 * (NBK_N + NBK_C) + (NBK_N + 1) + (NBK_C + 1)];
__device__ int   g_beid_n[NE];
__device__ int   g_beid_c[NEC];

// g_ints layout offsets
#define OFF_DEG_DST  0
#define OFF_DEG_CDST (NN)
#define OFF_DEG_CID  (NN + NCL)
#define OFF_DEG_NID  (NN + 2 * NCL)
#define OFF_BCNT_N   (2 * NN + 2 * NCL)
#define OFF_BCNT_C   (OFF_BCNT_N + NBK_N)
#define OFF_CUR_N    (OFF_BCNT_C + NBK_C)
#define OFF_CUR_C    (OFF_CUR_N + NBK_N)
#define OFF_BOFF_N   (OFF_CUR_C + NBK_C)
#define OFF_BOFF_C   (OFF_BOFF_N + NBK_N + 1)
#define ZERO_COUNT   (OFF_BOFF_N)   // zero everything before boff

// ---------------- f32x2 packed helpers ------------------------------------------
__device__ __forceinline__ u64 pk2(float v) {
    u64 r; asm("mov.b64 %0,{%1,%1};" : "=l"(r) : "f"(v)); return r;
}
__device__ __forceinline__ u64 fma2(u64 a, u64 b, u64 c) {
    u64 d; asm("fma.rn.f32x2 %0,%1,%2,%3;" : "=l"(d) : "l"(a), "l"(b), "l"(c)); return d;
}

// ---------------- setup kernels --------------------------------------------------
__global__ void k_zero_setup(int* __restrict__ p, int n) {
    int i = blockIdx.x * blockDim.x + threadIdx.x;
    if (i < n) p[i] = 0;
}

__global__ void k_setup_count(const int* __restrict__ src, const int* __restrict__ dst,
                              const int* __restrict__ csrc, const int* __restrict__ cdst,
                              const int* __restrict__ nid, const int* __restrict__ cid,
                              int* __restrict__ ints) {
    int i = blockIdx.x * blockDim.x + threadIdx.x;
    if (i < NE) {
        atomicAdd(&ints[OFF_DEG_DST + dst[i]], 1);
        atomicAdd(&ints[OFF_BCNT_N + (src[i] >> 7)], 1);
    } else if (i < NE + NEC) {
        int j = i - NE;
        atomicAdd(&ints[OFF_DEG_CDST + cdst[j]], 1);
        atomicAdd(&ints[OFF_BCNT_C + (csrc[j] >> 7)], 1);
    } else if (i < NE + NEC + NA) {
        int j = i - NE - NEC;
        atomicAdd(&ints[OFF_DEG_CID + cid[j]], 1);
        atomicAdd(&ints[OFF_DEG_NID + nid[j]], 1);
    }
}

// single-block scans: block 0 -> node buckets, block 1 -> clique buckets
__global__ void k_scan(int* __restrict__ ints) {
    __shared__ int s[256];
    int n      = blockIdx.x == 0 ? NBK_N : NBK_C;
    int* cnt   = ints + (blockIdx.x == 0 ? OFF_BCNT_N : OFF_BCNT_C);
    int* off   = ints + (blockIdx.x == 0 ? OFF_BOFF_N : OFF_BOFF_C);
    int t = threadIdx.x;
    s[t] = (t < n) ? cnt[t] : 0;
    __syncthreads();
    for (int d = 1; d < 256; d <<= 1) {
        int add = (t >= d) ? s[t - d] : 0;
        __syncthreads();
        s[t] += add;
        __syncthreads();
    }
    if (t == 0) off[0] = 0;
    if (t < n) off[t + 1] = s[t];
}

__global__ void k_fill(const int* __restrict__ src, const int* __restrict__ csrc,
                       int* __restrict__ ints,
                       int* __restrict__ beid_n, int* __restrict__ beid_c) {
    int i = blockIdx.x * blockDim.x + threadIdx.x;
    if (i < NE) {
        int b = src[i] >> 7;
        int pos = ints[OFF_BOFF_N + b] + atomicAdd(&ints[OFF_CUR_N + b], 1);
        beid_n[pos] = i;
    } else if (i < NE + NEC) {
        int j = i - NE;
        int b = csrc[j] >> 7;
        int pos = ints[OFF_BOFF_C + b] + atomicAdd(&ints[OFF_CUR_C + b], 1);
        beid_c[pos] = j;
    }
}

// ---------------- edge MLP (+ tail zero) ------------------------------------------
__global__ void k_edge_mlp_zero(int nE, const float* __restrict__ ef,
                                const float* __restrict__ w1, const float* __restrict__ b1,
                                float* __restrict__ hout,
                                float* __restrict__ zptr, int zn, int mlpBlocks) {
    if ((int)blockIdx.x >= mlpBlocks) {
        int i = (blockIdx.x - mlpBlocks) * blockDim.x + threadIdx.x;
        if (i < zn) zptr[i] = 0.f;
        return;
    }
    int e = (blockIdx.x * blockDim.x + threadIdx.x) >> 5;
    int lane = threadIdx.x & 31;
    if (e >= nE) return;
    float ev = (lane < EDIM) ? ef[(size_t)e * EDIM + lane] : 0.f;
    float acc = b1[lane];
#pragma unroll
    for (int j = 0; j < EDIM; j++)
        acc += __shfl_sync(0xffffffffu, ev, j) * w1[j * HD + lane];
    hout[(size_t)e * HD + lane] = fmaxf(acc, 0.f);
}

// ---------------- FUSED: per-block P-tile gemm in smem + edge messages ------------
// P[n, k*32+o] = sum_i X[n,i] * w2[k*1024 + i*32 + o]
// Q[n, o]      = sum_i X[n,i] * b2[i*32 + o]
// msg[e,o] = Q[src,o] + sum_k h[e,k] * P[src, k*32+o];  atomicAdd agg[dst,o]
// Chunked over o (4 chunks of 8): smem Ptile cols c = k*8 + oo.
#define XS 132
#define TS 256
#define PT 260
#define QT 33
#define SMEM_FLOATS (32 * XS + 32 * TS + TILE * PT + TILE * QT)

__global__ __launch_bounds__(512, 1)
void k_fused(const float* __restrict__ X, int nrows,
             const float* __restrict__ w2, const float* __restrict__ b2,
             const int* __restrict__ src, const int* __restrict__ dst,
             const float* __restrict__ h,
             const int* __restrict__ boff, const int* __restrict__ beid,
             float* __restrict__ agg) {
    extern __shared__ float sm[];
    float* Xs = sm;                    // [32][XS]  X transposed
    float* Ts = sm + 32 * XS;          // [32][TS]  permuted w2 chunk
    float* Pt = Ts + 32 * TS;          // [TILE][PT] P tile chunk
    float* Qt = Pt + TILE * PT;        // [TILE][QT] Q tile
    float* b2s = Pt;                   // reuse Pt space for b2 staging (first 1024)

    int t = threadIdx.x;
    int base = blockIdx.x * TILE;

    // load X tile transposed + stage b2
    for (int j = t; j < TILE * 8; j += 512) {   // TILE*8 float4 loads
        int r = j >> 3, iv = (j & 7) * 4;
        float4 v = make_float4(0.f, 0.f, 0.f, 0.f);
        if (base + r < nrows) v = *(const float4*)(X + (size_t)(base + r) * HD + iv);
        Xs[(iv + 0) * XS + r] = v.x;
        Xs[(iv + 1) * XS + r] = v.y;
        Xs[(iv + 2) * XS + r] = v.z;
        Xs[(iv + 3) * XS + r] = v.w;
    }
    for (int j = t; j < HD * HD; j += 512) b2s[j] = b2[j];
    __syncthreads();

    // Qtile: thread -> (n = t>>2, og = (t&3)*8)
    {
        int n = t >> 2, og = (t & 3) * 8;
        float q[8];
#pragma unroll
        for (int j = 0; j < 8; j++) q[j] = 0.f;
#pragma unroll
        for (int i = 0; i < HD; i++) {
            float xv = Xs[i * XS + n];
            float4 b0 = *(const float4*)&b2s[i * HD + og];
            float4 b1 = *(const float4*)&b2s[i * HD + og + 4];
            q[0] += xv * b0.x; q[1] += xv * b0.y; q[2] += xv * b0.z; q[3] += xv * b0.w;
            q[4] += xv * b1.x; q[5] += xv * b1.y; q[6] += xv * b1.z; q[7] += xv * b1.w;
        }
#pragma unroll
        for (int j = 0; j < 8; j++) Qt[n * QT + og + j] = q[j];
    }
    __syncthreads();   // Qt complete; b2s (Pt space) free for gemm

    int bstart = boff[blockIdx.x];
    int nEb    = boff[blockIdx.x + 1] - bstart;
    int ty4  = (t >> 4) * 4;     // row base (0..124)
    int tx16 = (t & 15) * 16;    // col base (0..240)
    int w = t >> 5, lane = t & 31, eg = lane >> 3, oo = lane & 7;

    for (int oc = 0; oc < 4; oc++) {
        // load Ts: Ts[i][c] = w2[(c>>3)*1024 + i*32 + oc*8 + (c&7)]
        for (int j = t; j < 2048; j += 512) {
            int i = j >> 6, c4 = j & 63;
            int k = c4 >> 1, oob = (c4 & 1) * 4;
            float4 v = *(const float4*)(w2 + k * (HD * HD) + i * HD + oc * 8 + oob);
            *(float4*)&Ts[i * TS + c4 * 4] = v;
        }
        __syncthreads();

        // gemm: Pt[TILE x 256] = Xs^T(TILE x 32) @ Ts(32 x 256), FFMA2
        {
            u64 acc[4][8];
#pragma unroll
            for (int r = 0; r < 4; r++)
#pragma unroll
                for (int j = 0; j < 8; j++) acc[r][j] = 0ULL;
#pragma unroll
            for (int i = 0; i < HD; i++) {
                float4 a4 = *(const float4*)&Xs[i * XS + ty4];
                u64 ad0 = pk2(a4.x), ad1 = pk2(a4.y), ad2 = pk2(a4.z), ad3 = pk2(a4.w);
                const u64* bp = (const u64*)&Ts[i * TS + tx16];
#pragma unroll
                for (int j = 0; j < 8; j++) {
                    u64 b = bp[j];
                    acc[0][j] = fma2(ad0, b, acc[0][j]);
                    acc[1][j] = fma2(ad1, b, acc[1][j]);
                    acc[2][j] = fma2(ad2, b, acc[2][j]);
                    acc[3][j] = fma2(ad3, b, acc[3][j]);
                }
            }
#pragma unroll
            for (int r = 0; r < 4; r++) {
                u64* pd = (u64*)&Pt[(ty4 + r) * PT + tx16];
#pragma unroll
                for (int j = 0; j < 8; j++) pd[j] = acc[r][j];
            }
        }
        __syncthreads();

        // edge phase: 4 edges per warp, 8 o-lanes per edge
        for (int eb = w * 4 + eg; eb < nEb; eb += 64) {
            int e = beid[bstart + eb];
            int s = src[e] - base;
            int d = dst[e];
            const float* hp = h + (size_t)e * HD;
            float msg = Qt[s * QT + oc * 8 + oo];
#pragma unroll
            for (int k = 0; k < HD; k++)
                msg += hp[k] * Pt[s * PT + k * 8 + oo];
            atomicAdd(&agg[(size_t)d * HD + oc * 8 + oo], msg);
        }
        __syncthreads();
    }
}

// ---------------- finalize + project + tail-zero ----------------------------------
__global__ void k_finalize_proj(const float* __restrict__ Xin, float* __restrict__ Xout,
                                const float* __restrict__ agg, const int* __restrict__ deg,
                                const float* __restrict__ rw, const float* __restrict__ rb,
                                const float* __restrict__ pw, const float* __restrict__ pb,
                                float* __restrict__ m, int nrows, int rowBlocks,
                                float* __restrict__ zptr, int zn,
                                float* __restrict__ copy_out) {
    if ((int)blockIdx.x >= rowBlocks) {
        int i = (blockIdx.x - rowBlocks) * blockDim.x + threadIdx.x;
        if (i < zn) zptr[i] = 0.f;
        return;
    }
    __shared__ float Rs[HD][HD], Pw[HD][HD];
    for (int i = threadIdx.x; i < HD * HD; i += blockDim.x) {
        Rs[i >> 5][i & 31] = rw[i];
        Pw[i >> 5][i & 31] = pw[i];
    }
    __syncthreads();

    int r = (blockIdx.x * blockDim.x + threadIdx.x) >> 5;
    int lane = threadIdx.x & 31;
    if (r >= nrows) return;
    float xv = Xin[(size_t)r * HD + lane];
    float acc = rb[lane] + agg[(size_t)r * HD + lane] / fmaxf((float)deg[r], 1.f);
#pragma unroll
    for (int i = 0; i < HD; i++)
        acc += __shfl_sync(0xffffffffu, xv, i) * Rs[i][lane];
    float xn = fmaxf(acc, 0.f);
    Xout[(size_t)r * HD + lane] = xn;
    if (copy_out) copy_out[(size_t)r * HD + lane] = xn;
    float macc = pb[lane];
#pragma unroll
    for (int i = 0; i < HD; i++)
        macc += __shfl_sync(0xffffffffu, xn, i) * Pw[i][lane];
    m[(size_t)r * HD + lane] = macc;
}

// ---------------- scatter + mean residual -----------------------------------------
__global__ void k_scatter(int nA, const int* __restrict__ from, const int* __restrict__ to,
                          const float* __restrict__ m, float* __restrict__ agg) {
    int a = (blockIdx.x * blockDim.x + threadIdx.x) >> 5;
    int lane = threadIdx.x & 31;
    if (a >= nA) return;
    float v = m[(size_t)from[a] * HD + lane];
    atomicAdd(&agg[(size_t)to[a] * HD + lane], v);
}

__global__ void k_addmean(const float* __restrict__ in, float* __restrict__ out,
                          const float* __restrict__ agg, const int* __restrict__ deg,
                          int nrows) {
    int i = blockIdx.x * blockDim.x + threadIdx.x;
    if (i >= nrows * HD) return;
    out[i] = in[i] + agg[i] / fmaxf((float)deg[i >> 5], 1.f);
}

// ===================================================================================
static inline int cdiv(int a, int b) { return (a + b - 1) / b; }

extern "C" void kernel_launch(void* const* d_in, const int* in_sizes, int n_in,
                              void* d_out, int out_size) {
    const float* node_features   = (const float*)d_in[0];
    const int*   edge_index      = (const int*)d_in[1];
    const float* edge_features   = (const float*)d_in[2];
    const float* clique_features = (const float*)d_in[3];
    const int*   n2c_index       = (const int*)d_in[4];
    const int*   cedge_index     = (const int*)d_in[5];
    const float* cedge_features  = (const float*)d_in[6];
    const float* nn1_w  = (const float*)d_in[7];
    const float* nn1_b  = (const float*)d_in[8];
    const float* nn2_w  = (const float*)d_in[9];
    const float* nn2_b  = (const float*)d_in[10];
    const float* root_w = (const float*)d_in[11];
    const float* root_b = (const float*)d_in[12];
    const float* n2c_w  = (const float*)d_in[13];
    const float* n2c_b  = (const float*)d_in[14];
    const float* cnn1_w = (const float*)d_in[15];
    const float* cnn1_b = (const float*)d_in[16];
    const float* cnn2_w = (const float*)d_in[17];
    const float* cnn2_b = (const float*)d_in[18];
    const float* croot_w = (const float*)d_in[19];
    const float* croot_b = (const float*)d_in[20];
    const float* c2n_w  = (const float*)d_in[21];
    const float* c2n_b  = (const float*)d_in[22];
    float* out = (float*)d_out;

    const int* src  = edge_index;
    const int* dst  = edge_index + NE;
    const int* nid  = n2c_index;
    const int* cid  = n2c_index + NA;
    const int* csrc = cedge_index;
    const int* cdst = cedge_index + NEC;

    float *x, *c, *h, *aggn, *aggc, *m;
    int *ints, *beid_n, *beid_c;
    cudaGetSymbolAddress((void**)&x, g_x);
    cudaGetSymbolAddress((void**)&c, g_c);
    cudaGetSymbolAddress((void**)&h, g_h);
    cudaGetSymbolAddress((void**)&aggn, g_aggn);
    cudaGetSymbolAddress((void**)&aggc, g_aggc);
    cudaGetSymbolAddress((void**)&m, g_m);
    cudaGetSymbolAddress((void**)&ints, g_ints);
    cudaGetSymbolAddress((void**)&beid_n, g_beid_n);
    cudaGetSymbolAddress((void**)&beid_c, g_beid_c);

    const int* deg_dst  = ints + OFF_DEG_DST;
    const int* deg_cdst = ints + OFF_DEG_CDST;
    const int* deg_cid  = ints + OFF_DEG_CID;
    const int* deg_nid  = ints + OFF_DEG_NID;
    const int* boff_n   = ints + OFF_BOFF_N;
    const int* boff_c   = ints + OFF_BOFF_C;

    static bool attr_set = false;
    if (!attr_set) {
        cudaFuncSetAttribute(k_fused, cudaFuncAttributeMaxDynamicSharedMemorySize,
                             SMEM_FLOATS * 4);
        attr_set = true;
    }

    const int TB = 256;
    const size_t SMB = SMEM_FLOATS * 4;
    int mlpB_n = cdiv(NE * 32, TB);
    int mlpB_c = cdiv(NEC * 32, TB);
    int zB_n = cdiv(NN * HD, TB);
    int zB_c = cdiv(NCL * HD, TB);
    int finB_n = cdiv(NN * 32, TB);
    int finB_c = cdiv(NCL * 32, TB);

    // ---- setup (1-4) ----
    k_zero_setup<<<cdiv(ZERO_COUNT, TB), TB>>>(ints, ZERO_COUNT);
    k_setup_count<<<cdiv(NE + NEC + NA, TB), TB>>>(src, dst, csrc, cdst, nid, cid, ints);
    k_scan<<<2, 256>>>(ints);
    k_fill<<<cdiv(NE + NEC, TB), TB>>>(src, csrc, ints, beid_n, beid_c);

    for (int l = 0; l < 2; l++) {
        const float* xin = (l == 0) ? node_features : x;
        int po = l * HD * HD, bo = l * HD;

        // ---- node NNConv ----
        k_edge_mlp_zero<<<mlpB_n + zB_n, TB>>>(NE, edge_features, nn1_w + l * EDIM * HD,
                                               nn1_b + bo, h, aggn, NN * HD, mlpB_n);
        k_fused<<<NBK_N, 512, SMB>>>(xin, NN, nn2_w + l * HD * HD * HD, nn2_b + po,
                                     src, dst, h, boff_n, beid_n, aggn);
        k_finalize_proj<<<finB_n + zB_c, TB>>>(xin, x, aggn, deg_dst,
                                               root_w + po, root_b + bo,
                                               n2c_w + po, n2c_b + bo,
                                               m, NN, finB_n, aggc, NCL * HD, nullptr);
        // ---- Node2Clique ----
        k_scatter<<<cdiv(NA * 32, TB), TB>>>(NA, nid, cid, m, aggc);
        k_addmean<<<cdiv(NCL * HD, TB), TB>>>((l == 0) ? clique_features : c, c,
                                              aggc, deg_cid, NCL);

        // ---- clique NNConv ----
        k_edge_mlp_zero<<<mlpB_c + zB_c, TB>>>(NEC, cedge_features, cnn1_w + l * EDIM * HD,
                                               cnn1_b + bo, h, aggc, NCL * HD, mlpB_c);
        k_fused<<<NBK_C, 512, SMB>>>(c, NCL, cnn2_w + l * HD * HD * HD, cnn2_b + po,
                                     csrc, cdst, h, boff_c, beid_c, aggc);
        k_finalize_proj<<<finB_c + zB_n, TB>>>(c, c, aggc, deg_cdst,
                                               croot_w + po, croot_b + bo,
                                               c2n_w + po, c2n_b + bo,
                                               m, NCL, finB_c, aggn, NN * HD,
                                               (l == 1) ? (out + (size_t)NN * HD) : nullptr);
        // ---- Clique2Node ----
        k_scatter<<<cdiv(NA * 32, TB), TB>>>(NA, cid, nid, m, aggn);
        k_addmean<<<cdiv(NN * HD, TB), TB>>>(x, (l == 1) ? out : x, aggn, deg_nid, NN);
    }
}

// round 4
// speedup vs baseline: 2.4562x; 2.4562x over previous
#include <cuda_runtime.h>
#include <cstdint>

#define NN   25000
#define NE   100000
#define HD   32
#define NCL  8000
#define NA   50000
#define NEC  24000
#define EDIM 8

// ---------------- scratch (device globals; no dynamic allocation) -------------
__device__ float g_x[NN * HD];
__device__ float g_c[NCL * HD];
__device__ float g_h[NE * HD];
__device__ float g_P[(size_t)NN * HD * HD];    // 102.4 MB
__device__ float g_Q[NN * HD];
__device__ float g_aggn[NN * HD];
__device__ float g_aggc[NCL * HD];
__device__ float g_m[NN * HD];
__device__ int   g_deg[2 * NN + 2 * NCL];      // [dst | cdst | cid | nid]

// ---------------- setup ---------------------------------------------------------
__global__ void k_zero_deg(int* __restrict__ p, int n) {
    int i = blockIdx.x * blockDim.x + threadIdx.x;
    if (i < n) p[i] = 0;
}

// one kernel, all four degree counts
__global__ void k_count_all(const int* __restrict__ dst, const int* __restrict__ cdst,
                            const int* __restrict__ nid, const int* __restrict__ cid,
                            int* __restrict__ deg) {
    int i = blockIdx.x * blockDim.x + threadIdx.x;
    if (i < NE) {
        atomicAdd(&deg[dst[i]], 1);                       // deg_dst
    } else if (i < NE + NEC) {
        atomicAdd(&deg[NN + cdst[i - NE]], 1);            // deg_cdst
    } else if (i < NE + NEC + NA) {
        int j = i - NE - NEC;
        atomicAdd(&deg[NN + NCL + cid[j]], 1);            // deg_cid
        atomicAdd(&deg[NN + 2 * NCL + nid[j]], 1);        // deg_nid
    }
}

// ---------------- edge MLP + tail-zero ------------------------------------------
__global__ void k_edge_mlp_zero(int nE, const float* __restrict__ ef,
                                const float* __restrict__ w1, const float* __restrict__ b1,
                                float* __restrict__ hout,
                                float* __restrict__ zptr, int zn, int mlpBlocks) {
    if ((int)blockIdx.x >= mlpBlocks) {
        int i = (blockIdx.x - mlpBlocks) * blockDim.x + threadIdx.x;
        if (i < zn) zptr[i] = 0.f;
        return;
    }
    int e = (blockIdx.x * blockDim.x + threadIdx.x) >> 5;
    int lane = threadIdx.x & 31;
    if (e >= nE) return;
    float ev = (lane < EDIM) ? ef[(size_t)e * EDIM + lane] : 0.f;
    float acc = b1[lane];
#pragma unroll
    for (int j = 0; j < EDIM; j++)
        acc += __shfl_sync(0xffffffffu, ev, j) * w1[j * HD + lane];
    hout[(size_t)e * HD + lane] = fmaxf(acc, 0.f);
}

// ---------------- P = X @ T (permuted w2), identical to round-1 kernel ----------
// T[i, k*32+o] = w2[k*1024 + i*32 + o]; permutation folded into B-tile load.
__global__ __launch_bounds__(256, 2)
void k_gemmP(const float* __restrict__ X, int nrows,
             const float* __restrict__ w2, float* __restrict__ P) {
    __shared__ float As[HD][128];
    __shared__ float Bs[HD][128];
    int tid  = threadIdx.x;
    int row0 = blockIdx.x * 128;
    int col0 = blockIdx.y * 128;

    {
        int r = tid >> 3;
        int q = tid & 7;
        for (int rr = r; rr < 128; rr += 32) {
            int row = row0 + rr;
            float4 v = make_float4(0.f, 0.f, 0.f, 0.f);
            if (row < nrows) v = *(const float4*)(X + (size_t)row * HD + q * 4);
            As[q * 4 + 0][rr] = v.x;
            As[q * 4 + 1][rr] = v.y;
            As[q * 4 + 2][rr] = v.z;
            As[q * 4 + 3][rr] = v.w;
        }
    }
    {
        int r = tid >> 5;
        int q = tid & 31;
        int C = col0 + q * 4;
        int kcol = C >> 5, o = C & 31;
        for (int kk = r; kk < HD; kk += 8) {
            float4 v = *(const float4*)(w2 + kcol * (HD * HD) + kk * HD + o);
            *(float4*)&Bs[kk][q * 4] = v;
        }
    }
    __syncthreads();

    int tr = (tid >> 4) * 8;
    int tc = (tid & 15) * 8;
    float acc[8][8];
#pragma unroll
    for (int a = 0; a < 8; a++)
#pragma unroll
        for (int b = 0; b < 8; b++) acc[a][b] = 0.f;

#pragma unroll
    for (int k = 0; k < HD; k++) {
        float a[8], b[8];
        *(float4*)&a[0] = *(float4*)&As[k][tr];
        *(float4*)&a[4] = *(float4*)&As[k][tr + 4];
        *(float4*)&b[0] = *(float4*)&Bs[k][tc];
        *(float4*)&b[4] = *(float4*)&Bs[k][tc + 4];
#pragma unroll
        for (int i = 0; i < 8; i++)
#pragma unroll
            for (int j = 0; j < 8; j++)
                acc[i][j] += a[i] * b[j];
    }

#pragma unroll
    for (int i = 0; i < 8; i++) {
        int row = row0 + tr + i;
        if (row < nrows) {
            float* dstp = P + (size_t)row * (HD * HD) + col0 + tc;
            *(float4*)(dstp)     = make_float4(acc[i][0], acc[i][1], acc[i][2], acc[i][3]);
            *(float4*)(dstp + 4) = make_float4(acc[i][4], acc[i][5], acc[i][6], acc[i][7]);
        }
    }
}

// ---------------- Q = X @ b2 (per node), warp per row ----------------------------
__global__ void k_linear(const float* __restrict__ X, const float* __restrict__ W,
                         float* __restrict__ out, int nrows) {
    int r = (blockIdx.x * blockDim.x + threadIdx.x) >> 5;
    int lane = threadIdx.x & 31;
    if (r >= nrows) return;
    float xv = X[(size_t)r * HD + lane];
    float acc = 0.f;
#pragma unroll
    for (int i = 0; i < HD; i++)
        acc += __shfl_sync(0xffffffffu, xv, i) * W[i * HD + lane];
    out[(size_t)r * HD + lane] = acc;
}

// ---------------- per-edge message + scatter-add, vectorized --------------------
// lane = (k-quad = lane>>3, o-group = lane&7). P read via LDG.128, 512B/warp/iter.
__global__ void k_edge_msg(int nE, const int* __restrict__ src, const int* __restrict__ dst,
                           const float* __restrict__ h, const float* __restrict__ P,
                           const float* __restrict__ Q, float* __restrict__ agg) {
    int e = (blockIdx.x * blockDim.x + threadIdx.x) >> 5;
    int lane = threadIdx.x & 31;
    if (e >= nE) return;
    int s = src[e];
    int d = dst[e];
    float hv = h[(size_t)e * HD + lane];            // lane = k for the broadcast source
    const float4* Pr = (const float4*)(P + (size_t)s * (HD * HD));
    int kq = lane >> 3;          // 0..3
    int og = lane & 7;           // o-group: covers o = og*4 .. og*4+3

    float a0 = 0.f, a1 = 0.f, a2 = 0.f, a3 = 0.f;
#pragma unroll
    for (int it = 0; it < 8; it++) {
        int k = it * 4 + kq;
        float hk = __shfl_sync(0xffffffffu, hv, k);
        float4 v = Pr[k * 8 + og];                  // warp covers 512B contiguous
        a0 += hk * v.x; a1 += hk * v.y; a2 += hk * v.z; a3 += hk * v.w;
    }
    // reduce across the 4 k-quads (lanes differing in bits 3,4)
#pragma unroll
    for (int m = 8; m <= 16; m <<= 1) {
        a0 += __shfl_xor_sync(0xffffffffu, a0, m);
        a1 += __shfl_xor_sync(0xffffffffu, a1, m);
        a2 += __shfl_xor_sync(0xffffffffu, a2, m);
        a3 += __shfl_xor_sync(0xffffffffu, a3, m);
    }
    if (lane < 8) {
        float4 q = *(const float4*)(Q + (size_t)s * HD + lane * 4);
        float* ag = agg + (size_t)d * HD + lane * 4;
        atomicAdd(ag + 0, a0 + q.x);
        atomicAdd(ag + 1, a1 + q.y);
        atomicAdd(ag + 2, a2 + q.z);
        atomicAdd(ag + 3, a3 + q.w);
    }
}

// ---------------- finalize + project + tail-zero ---------------------------------
// Xout = relu(agg/deg + Xin@rw + rb);  m = Xout@pw + pb;  optional copy of Xout.
__global__ void k_finalize_proj(const float* __restrict__ Xin, float* __restrict__ Xout,
                                const float* __restrict__ agg, const int* __restrict__ deg,
                                const float* __restrict__ rw, const float* __restrict__ rb,
                                const float* __restrict__ pw, const float* __restrict__ pb,
                                float* __restrict__ m, int nrows, int rowBlocks,
                                float* __restrict__ zptr, int zn,
                                float* __restrict__ copy_out) {
    if ((int)blockIdx.x >= rowBlocks) {
        int i = (blockIdx.x - rowBlocks) * blockDim.x + threadIdx.x;
        if (i < zn) zptr[i] = 0.f;
        return;
    }
    __shared__ float Rs[HD][HD], Pw[HD][HD];
    for (int i = threadIdx.x; i < HD * HD; i += blockDim.x) {
        Rs[i >> 5][i & 31] = rw[i];
        Pw[i >> 5][i & 31] = pw[i];
    }
    __syncthreads();

    int r = (blockIdx.x * blockDim.x + threadIdx.x) >> 5;
    int lane = threadIdx.x & 31;
    if (r >= nrows) return;
    float xv = Xin[(size_t)r * HD + lane];
    float acc = rb[lane] + agg[(size_t)r * HD + lane] / fmaxf((float)deg[r], 1.f);
#pragma unroll
    for (int i = 0; i < HD; i++)
        acc += __shfl_sync(0xffffffffu, xv, i) * Rs[i][lane];
    float xn = fmaxf(acc, 0.f);
    Xout[(size_t)r * HD + lane] = xn;
    if (copy_out) copy_out[(size_t)r * HD + lane] = xn;
    float macc = pb[lane];
#pragma unroll
    for (int i = 0; i < HD; i++)
        macc += __shfl_sync(0xffffffffu, xn, i) * Pw[i][lane];
    m[(size_t)r * HD + lane] = macc;
}

// ---------------- scatter + mean residual ----------------------------------------
__global__ void k_scatter(int nA, const int* __restrict__ from, const int* __restrict__ to,
                          const float* __restrict__ m, float* __restrict__ agg) {
    int a = (blockIdx.x * blockDim.x + threadIdx.x) >> 5;
    int lane = threadIdx.x & 31;
    if (a >= nA) return;
    float v = m[(size_t)from[a] * HD + lane];
    atomicAdd(&agg[(size_t)to[a] * HD + lane], v);
}

__global__ void k_addmean(const float* __restrict__ in, float* __restrict__ out,
                          const float* __restrict__ agg, const int* __restrict__ deg,
                          int nrows) {
    int i = blockIdx.x * blockDim.x + threadIdx.x;
    if (i >= nrows * HD) return;
    out[i] = in[i] + agg[i] / fmaxf((float)deg[i >> 5], 1.f);
}

// ===================================================================================
static inline int cdiv(int a, int b) { return (a + b - 1) / b; }

extern "C" void kernel_launch(void* const* d_in, const int* in_sizes, int n_in,
                              void* d_out, int out_size) {
    const float* node_features   = (const float*)d_in[0];
    const int*   edge_index      = (const int*)d_in[1];
    const float* edge_features   = (const float*)d_in[2];
    const float* clique_features = (const float*)d_in[3];
    const int*   n2c_index       = (const int*)d_in[4];
    const int*   cedge_index     = (const int*)d_in[5];
    const float* cedge_features  = (const float*)d_in[6];
    const float* nn1_w  = (const float*)d_in[7];
    const float* nn1_b  = (const float*)d_in[8];
    const float* nn2_w  = (const float*)d_in[9];
    const float* nn2_b  = (const float*)d_in[10];
    const float* root_w = (const float*)d_in[11];
    const float* root_b = (const float*)d_in[12];
    const float* n2c_w  = (const float*)d_in[13];
    const float* n2c_b  = (const float*)d_in[14];
    const float* cnn1_w = (const float*)d_in[15];
    const float* cnn1_b = (const float*)d_in[16];
    const float* cnn2_w = (const float*)d_in[17];
    const float* cnn2_b = (const float*)d_in[18];
    const float* croot_w = (const float*)d_in[19];
    const float* croot_b = (const float*)d_in[20];
    const float* c2n_w  = (const float*)d_in[21];
    const float* c2n_b  = (const float*)d_in[22];
    float* out = (float*)d_out;

    const int* src  = edge_index;
    const int* dst  = edge_index + NE;
    const int* nid  = n2c_index;
    const int* cid  = n2c_index + NA;
    const int* csrc = cedge_index;
    const int* cdst = cedge_index + NEC;

    float *x, *c, *h, *P, *Q, *aggn, *aggc, *m;
    int* deg;
    cudaGetSymbolAddress((void**)&x, g_x);
    cudaGetSymbolAddress((void**)&c, g_c);
    cudaGetSymbolAddress((void**)&h, g_h);
    cudaGetSymbolAddress((void**)&P, g_P);
    cudaGetSymbolAddress((void**)&Q, g_Q);
    cudaGetSymbolAddress((void**)&aggn, g_aggn);
    cudaGetSymbolAddress((void**)&aggc, g_aggc);
    cudaGetSymbolAddress((void**)&m, g_m);
    cudaGetSymbolAddress((void**)&deg, g_deg);
    const int* deg_dst  = deg;
    const int* deg_cdst = deg + NN;
    const int* deg_cid  = deg + NN + NCL;
    const int* deg_nid  = deg + NN + 2 * NCL;

    const int TB = 256;
    const int DEG_N = 2 * NN + 2 * NCL;
    dim3 gemmGridN(cdiv(NN, 128), 8);
    dim3 gemmGridC(cdiv(NCL, 128), 8);
    int mlpB_n = cdiv(NE * 32, TB);
    int mlpB_c = cdiv(NEC * 32, TB);
    int zB_n = cdiv(NN * HD, TB);
    int zB_c = cdiv(NCL * HD, TB);
    int finB_n = cdiv(NN * 32, TB);
    int finB_c = cdiv(NCL * 32, TB);

    // ---- setup: launches #1-2 ----
    k_zero_deg<<<cdiv(DEG_N, TB), TB>>>(deg, DEG_N);
    k_count_all<<<cdiv(NE + NEC + NA, TB), TB>>>(dst, cdst, nid, cid, deg);

    for (int l = 0; l < 2; l++) {
        const float* xin = (l == 0) ? node_features : x;
        const float* cin = (l == 0) ? clique_features : c;
        int po = l * HD * HD, bo = l * HD;

        // ---- node NNConv ----
        // launch #3 (l=0): edge mlp + zero aggn
        k_edge_mlp_zero<<<mlpB_n + zB_n, TB>>>(NE, edge_features, nn1_w + l * EDIM * HD,
                                               nn1_b + bo, h, aggn, NN * HD, mlpB_n);
        // launch #4 (l=0): gemmP  <-- profiled by ncu
        k_gemmP<<<gemmGridN, 256>>>(xin, NN, nn2_w + l * HD * HD * HD, P);
        k_linear<<<cdiv(NN * 32, TB), TB>>>(xin, nn2_b + po, Q, NN);
        k_edge_msg<<<cdiv(NE * 32, TB), TB>>>(NE, src, dst, h, P, Q, aggn);
        // finalize x + project m = x@n2c; tail zeros aggc for the n2c scatter
        k_finalize_proj<<<finB_n + zB_c, TB>>>(xin, x, aggn, deg_dst,
                                               root_w + po, root_b + bo,
                                               n2c_w + po, n2c_b + bo,
                                               m, NN, finB_n, aggc, NCL * HD, nullptr);
        // ---- Node2Clique ----
        k_scatter<<<cdiv(NA * 32, TB), TB>>>(NA, nid, cid, m, aggc);
        k_addmean<<<cdiv(NCL * HD, TB), TB>>>(cin, c, aggc, deg_cid, NCL);

        // ---- clique NNConv ----
        k_edge_mlp_zero<<<mlpB_c + zB_c, TB>>>(NEC, cedge_features, cnn1_w + l * EDIM * HD,
                                               cnn1_b + bo, h, aggc, NCL * HD, mlpB_c);
        k_gemmP<<<gemmGridC, 256>>>(c, NCL, cnn2_w + l * HD * HD * HD, P);
        k_linear<<<cdiv(NCL * 32, TB), TB>>>(c, cnn2_b + po, Q, NCL);
        k_edge_msg<<<cdiv(NEC * 32, TB), TB>>>(NEC, csrc, cdst, h, P, Q, aggc);
        // finalize c + project m = c@c2n; tail zeros aggn for the c2n scatter;
        // on the last layer also copy final c into the output buffer
        k_finalize_proj<<<finB_c + zB_n, TB>>>(c, c, aggc, deg_cdst,
                                               croot_w + po, croot_b + bo,
                                               c2n_w + po, c2n_b + bo,
                                               m, NCL, finB_c, aggn, NN * HD,
                                               (l == 1) ? (out + (size_t)NN * HD) : nullptr);
        // ---- Clique2Node ----
        k_scatter<<<cdiv(NA * 32, TB), TB>>>(NA, cid, nid, m, aggn);
        k_addmean<<<cdiv(NN * HD, TB), TB>>>(x, (l == 1) ? out : x, aggn, deg_nid, NN);
    }
}